// round 1
// baseline (speedup 1.0000x reference)
#include <cuda_runtime.h>
#include <math.h>

#define BATCH 8192

// ---------------- scratch (static device globals; no allocation) ----------------
__device__ float g_mag[BATCH * 4 * 129];   // [b][t][f]
__device__ float g_e1 [BATCH * 4 * 128];   // [b][t][o]
__device__ float g_x  [BATCH * 128];       // enc4 output = LSTM input x
__device__ float g_gt [BATCH * 512];       // gate pre-activations [b][mat*128+o], mat: i,f,g,o

// ---------------- Kernel A: reflect-pad + STFT conv + magnitude ----------------
// grid 512, block 256, 16 batches/CTA. Each thread: (b_local, f_lane), register-
// blocked over the 4 frames. Basis streamed via __ldg float4 (L1/L2 broadcast).
__global__ __launch_bounds__(256) void k_stft(const float* __restrict__ audio,
                                              const float* __restrict__ basis) {
    __shared__ float sa[16 * 641];  // stride 641 (odd) -> conflict-free lane access
    const int b0 = blockIdx.x * 16;
    const int tid = threadIdx.x;
    for (int i = tid; i < 16 * 640; i += 256) {
        int bl = i / 640, n = i - bl * 640;
        int src = (n < 576) ? n : (1150 - n);       // reflect pad: padded[576+i]=audio[574-i]
        sa[bl * 641 + n] = audio[(b0 + bl) * 576 + src];
    }
    __syncthreads();
    const int bl = tid & 15;
    const int fl = tid >> 4;
    const float* arow = sa + bl * 641;
    for (int f = fl; f < 129; f += 16) {
        const float4* br = (const float4*)(basis + f * 256);
        const float4* bi = (const float4*)(basis + (f + 129) * 256);
        float rr[4] = {0.f, 0.f, 0.f, 0.f};
        float ii[4] = {0.f, 0.f, 0.f, 0.f};
#pragma unroll 4
        for (int n4 = 0; n4 < 64; n4++) {
            float4 wr = __ldg(br + n4);
            float4 wi = __ldg(bi + n4);
            int n = n4 * 4;
#pragma unroll
            for (int t = 0; t < 4; t++) {
                const float* a = arow + t * 128 + n;
                rr[t] += wr.x * a[0] + wr.y * a[1] + wr.z * a[2] + wr.w * a[3];
                ii[t] += wi.x * a[0] + wi.y * a[1] + wi.z * a[2] + wi.w * a[3];
            }
        }
#pragma unroll
        for (int t = 0; t < 4; t++)
            g_mag[((b0 + bl) * 4 + t) * 129 + f] = sqrtf(rr[t] * rr[t] + ii[t] * ii[t]);
    }
}

// ---------------- Kernel B: enc1 (129->128 ch, k=3, pad 1, len 4) ----------------
// grid 512, block 256, 16 batches/CTA; thread owns (b_local, o_lane), register-
// blocked over the 4 output positions (reuses each weight triple for 10 FMAs).
__global__ __launch_bounds__(256) void k_enc1(const float* __restrict__ w1,
                                              const float* __restrict__ b1) {
    __shared__ float sm[4 * 16 * 129];  // [(t*16+bl)*129 + c]; bl stride 129 (odd)
    const int b0 = blockIdx.x * 16;
    const int tid = threadIdx.x;
    for (int i = tid; i < 16 * 516; i += 256) {
        int bl = i / 516; int r = i - bl * 516;
        int t = r / 129;  int c = r - t * 129;
        sm[(t * 16 + bl) * 129 + c] = g_mag[b0 * 516 + i];
    }
    __syncthreads();
    const int bl = tid & 15, ol = tid >> 4;
    const float* m0p = sm + (0 * 16 + bl) * 129;
    const float* m1p = sm + (1 * 16 + bl) * 129;
    const float* m2p = sm + (2 * 16 + bl) * 129;
    const float* m3p = sm + (3 * 16 + bl) * 129;
    for (int oi = 0; oi < 8; oi++) {
        int o = oi * 16 + ol;
        const float* w = w1 + o * 387;  // [c][k], k fastest
        float bias = __ldg(b1 + o);
        float a0 = bias, a1 = bias, a2 = bias, a3 = bias;
        for (int c = 0; c < 129; c++) {
            float w0 = __ldg(w + c * 3), wv1 = __ldg(w + c * 3 + 1), w2 = __ldg(w + c * 3 + 2);
            float e0 = m0p[c], e1 = m1p[c], e2 = m2p[c], e3 = m3p[c];
            a0 += wv1 * e0 + w2 * e1;
            a1 += w0 * e0 + wv1 * e1 + w2 * e2;
            a2 += w0 * e1 + wv1 * e2 + w2 * e3;
            a3 += w0 * e2 + wv1 * e3;
        }
        int base = (b0 + bl) * 512 + o;
        g_e1[base      ] = fmaxf(a0, 0.f);
        g_e1[base + 128] = fmaxf(a1, 0.f);
        g_e1[base + 256] = fmaxf(a2, 0.f);
        g_e1[base + 384] = fmaxf(a3, 0.f);
    }
}

// ---------------- Kernel C0: enc2 (s2) + enc3 (s2) + enc4 -> x ----------------
// grid 512, block 256, 16 batches/CTA. Warp = 16 b-lanes x 2 o-slots: weight
// loads are warp-broadcast (2 addrs), smem lanes conflict-free ([..][16] inner).
__global__ __launch_bounds__(256) void k_enc234(const float* __restrict__ w2, const float* __restrict__ b2,
                                                const float* __restrict__ w3, const float* __restrict__ b3,
                                                const float* __restrict__ w4, const float* __restrict__ b4) {
    __shared__ float se1[4 * 128 * 16];  // [(t*128+c)*16 + bl]
    __shared__ float so2[2 * 64 * 16];   // [(t2*64+o)*16 + bl]
    __shared__ float so3[64 * 16];
    const int b0 = blockIdx.x * 16;
    const int tid = threadIdx.x;
    for (int i = tid; i < 16 * 512; i += 256) {
        int bl = i / 512; int r = i - bl * 512;  // r = t*128 + c
        se1[r * 16 + bl] = g_e1[b0 * 512 + i];
    }
    __syncthreads();
    const int lane = tid & 31;
    const int bl = lane & 15;
    const int ow = lane >> 4;
    const int o_lane = (tid >> 5) * 2 + ow;  // 0..15
    // enc2: out len 2 (t2=0 uses pad,t0,t1 ; t2=1 uses t1,t2,t3)
    for (int j = 0; j < 4; j++) {
        int o = j * 16 + o_lane;
        const float* w = w2 + o * 384;
        float bias = __ldg(b2 + o);
        float a0 = bias, a1 = bias;
        for (int c = 0; c < 128; c++) {
            float w0 = __ldg(w + c * 3), wv1 = __ldg(w + c * 3 + 1), wv2 = __ldg(w + c * 3 + 2);
            float e0 = se1[c * 16 + bl];
            float e1 = se1[(128 + c) * 16 + bl];
            float e2 = se1[(256 + c) * 16 + bl];
            float e3 = se1[(384 + c) * 16 + bl];
            a0 += wv1 * e0 + wv2 * e1;
            a1 += w0 * e1 + wv1 * e2 + wv2 * e3;
        }
        so2[o * 16 + bl]        = fmaxf(a0, 0.f);
        so2[(64 + o) * 16 + bl] = fmaxf(a1, 0.f);
    }
    __syncthreads();
    // enc3: out len 1, taps k=1 (t2=0), k=2 (t2=1)
    for (int j = 0; j < 4; j++) {
        int o = j * 16 + o_lane;
        const float* w = w3 + o * 192;
        float a = __ldg(b3 + o);
        for (int c = 0; c < 64; c++)
            a += __ldg(w + c * 3 + 1) * so2[c * 16 + bl] +
                 __ldg(w + c * 3 + 2) * so2[(64 + c) * 16 + bl];
        so3[o * 16 + bl] = fmaxf(a, 0.f);
    }
    __syncthreads();
    // enc4: out len 1, only center tap k=1
    for (int j = 0; j < 8; j++) {
        int o = j * 16 + o_lane;
        const float* w = w4 + o * 192;
        float a = __ldg(b4 + o);
        for (int c = 0; c < 64; c++)
            a += __ldg(w + c * 3 + 1) * so3[c * 16 + bl];
        g_x[(b0 + bl) * 128 + o] = fmaxf(a, 0.f);
    }
}

// ---------------- Kernel C1: LSTM gate GEMM  pre[b][o'] = [x|h] . [W|U] ----------------
// M=8192, N=512, K=256. 64x64 tiles, BK=16, 4x4 micro-tile per thread.
__global__ __launch_bounds__(256) void k_gates(const float* __restrict__ h,
    const float* __restrict__ wi, const float* __restrict__ wf,
    const float* __restrict__ wg, const float* __restrict__ wo,
    const float* __restrict__ ui, const float* __restrict__ uf,
    const float* __restrict__ ug, const float* __restrict__ uo) {
    __shared__ float As[16][64];
    __shared__ float Bs[16][64];
    const int m0 = blockIdx.x * 64;
    const int n0 = blockIdx.y * 64;
    const int mat = n0 >> 7;  // each 64-wide N block lies inside one 128-wide matrix
    const float* W = (mat == 0) ? wi : (mat == 1) ? wf : (mat == 2) ? wg : wo;
    const float* U = (mat == 0) ? ui : (mat == 1) ? uf : (mat == 2) ? ug : uo;
    const int tid = threadIdx.x;
    const int tm = (tid & 15) * 4, tn = (tid >> 4) * 4;
    float acc[4][4] = {};
    for (int k0 = 0; k0 < 256; k0 += 16) {
        const float* Asrc = (k0 < 128) ? g_x : h;
        const float* Bsrc = (k0 < 128) ? W : U;
        const int kbase = k0 & 127;
        for (int i = tid; i < 64 * 16; i += 256) {
            int row = i >> 4, kk = i & 15;
            As[kk][row] = Asrc[(m0 + row) * 128 + kbase + kk];
            Bs[kk][row] = Bsrc[((n0 + row) & 127) * 128 + kbase + kk];
        }
        __syncthreads();
#pragma unroll
        for (int kk = 0; kk < 16; kk++) {
            float4 av = *(const float4*)&As[kk][tm];
            float4 bv = *(const float4*)&Bs[kk][tn];
            float a[4] = {av.x, av.y, av.z, av.w};
            float b[4] = {bv.x, bv.y, bv.z, bv.w};
#pragma unroll
            for (int r = 0; r < 4; r++)
#pragma unroll
                for (int c = 0; c < 4; c++) acc[r][c] += a[r] * b[c];
        }
        __syncthreads();
    }
#pragma unroll
    for (int r = 0; r < 4; r++) {
        float4 v = make_float4(acc[r][0], acc[r][1], acc[r][2], acc[r][3]);
        *(float4*)&g_gt[(m0 + tm + r) * 512 + n0 + tn] = v;
    }
}

// ---------------- Kernel C2: activations, LSTM cell, head ----------------
__global__ __launch_bounds__(128) void k_final(const float* __restrict__ cin,
    const float* __restrict__ bxi, const float* __restrict__ bxf,
    const float* __restrict__ bxg, const float* __restrict__ bxo,
    const float* __restrict__ bhi, const float* __restrict__ bhf,
    const float* __restrict__ bhg, const float* __restrict__ bho,
    const float* __restrict__ cw, const float* __restrict__ cb,
    float* __restrict__ out, int writeHC) {
    const int b = blockIdx.x, o = threadIdx.x;
    const float* g = g_gt + b * 512;
    float pi = g[o]       + __ldg(bxi + o) + __ldg(bhi + o);
    float pf = g[128 + o] + __ldg(bxf + o) + __ldg(bhf + o);
    float pg = g[256 + o] + __ldg(bxg + o) + __ldg(bhg + o);
    float po = g[384 + o] + __ldg(bxo + o) + __ldg(bho + o);
    float ig = 1.f / (1.f + expf(-pi));
    float fg = 1.f / (1.f + expf(-pf));
    float gg = tanhf(pg);
    float og = 1.f / (1.f + expf(-po));
    float co = fg * cin[b * 128 + o] + ig * gg;
    float ho = og * tanhf(co);
    if (writeHC) {
        out[BATCH + b * 128 + o] = ho;
        out[BATCH + BATCH * 128 + b * 128 + o] = co;
    }
    __shared__ float red[128];
    float y = ho > 0.f ? ho : 0.f;
    red[o] = y * __ldg(cw + o);
    __syncthreads();
    for (int s = 64; s > 0; s >>= 1) {
        if (o < s) red[o] += red[o + s];
        __syncthreads();
    }
    if (o == 0) out[b] = 1.f / (1.f + expf(-(red[0] + cb[0])));
}

// ---------------- launch ----------------
extern "C" void kernel_launch(void* const* d_in, const int* in_sizes, int n_in,
                              void* d_out, int out_size) {
    const float* audio = (const float*)d_in[0];
    const float* h     = (const float*)d_in[1];
    const float* cin   = (const float*)d_in[2];
    const float* basis = (const float*)d_in[3];
    const float* w1 = (const float*)d_in[4];  const float* b1 = (const float*)d_in[5];
    const float* w2 = (const float*)d_in[6];  const float* b2 = (const float*)d_in[7];
    const float* w3 = (const float*)d_in[8];  const float* b3 = (const float*)d_in[9];
    const float* w4 = (const float*)d_in[10]; const float* b4 = (const float*)d_in[11];
    const float* wi = (const float*)d_in[12]; const float* wf = (const float*)d_in[13];
    const float* wg = (const float*)d_in[14]; const float* wo = (const float*)d_in[15];
    const float* ui = (const float*)d_in[16]; const float* uf = (const float*)d_in[17];
    const float* ug = (const float*)d_in[18]; const float* uo = (const float*)d_in[19];
    const float* bxi = (const float*)d_in[20]; const float* bxf = (const float*)d_in[21];
    const float* bxg = (const float*)d_in[22]; const float* bxo = (const float*)d_in[23];
    const float* bhi = (const float*)d_in[24]; const float* bhf = (const float*)d_in[25];
    const float* bhg = (const float*)d_in[26]; const float* bho = (const float*)d_in[27];
    const float* cw  = (const float*)d_in[28]; const float* cb  = (const float*)d_in[29];
    float* out = (float*)d_out;
    int writeHC = (out_size >= BATCH * 257) ? 1 : 0;

    k_stft<<<512, 256>>>(audio, basis);
    k_enc1<<<512, 256>>>(w1, b1);
    k_enc234<<<512, 256>>>(w2, b2, w3, b3, w4, b4);
    dim3 gg(BATCH / 64, 512 / 64);
    k_gates<<<gg, 256>>>(h, wi, wf, wg, wo, ui, uf, ug, uo);
    k_final<<<BATCH, 128>>>(cin, bxi, bxf, bxg, bxo, bhi, bhf, bhg, bho,
                            cw, cb, out, writeHC);
}

// round 3
// speedup vs baseline: 2.0095x; 2.0095x over previous
#include <cuda_runtime.h>
#include <math.h>
#include <stdint.h>

#define BATCH 8192

// ---------------- scratch (static device globals; no allocation) ----------------
// A (im2col) matrices, fp32-holding-tf32 (rna-rounded)
__device__ float g_Astft[32768 * 256];
__device__ float g_A1   [32768 * 400];   // K=387 padded to 400
__device__ float g_A2   [16384 * 384];
__device__ float g_A3   [ 8192 * 192];
__device__ float g_A4   [ 8192 * 192];
__device__ float g_Ag   [ 8192 * 256];   // [x | h]
// B (packed weight) matrices [K][N]
__device__ float g_Bstft[256 * 320];     // cols: 2f=real, 2f+1=imag, pad>=258
__device__ float g_B1   [400 * 128];
__device__ float g_B2   [384 *  64];
__device__ float g_B3   [192 *  64];
__device__ float g_B4   [192 * 128];
__device__ float g_Bg   [256 * 512];
// activations
__device__ float g_mag[32768 * 129];     // [b*4+t][f]
__device__ float g_e1 [32768 * 128];
__device__ float g_e2 [16384 *  64];
__device__ float g_e3 [ 8192 *  64];
__device__ float g_gt [ 8192 * 512];     // gate pre-activations

__device__ __forceinline__ float rna(float x) {
    asm("cvt.rna.tf32.f32 %0, %1;" : "=f"(x) : "f"(x));
    return x;
}

// ================= prep kernels (im2col + weight packing, all rna-rounded) =================
__global__ void k_prepAstft(const float* __restrict__ audio) {
    int i = blockIdx.x * 256 + threadIdx.x;            // 32768*256 elems
    int row = i >> 8, k = i & 255;
    int b = row >> 2, t = row & 3;
    int s = t * 128 + k;
    int src = (s < 576) ? s : (1150 - s);              // reflect pad
    g_Astft[i] = rna(audio[b * 576 + src]);
}
__global__ void k_prepBstft(const float* __restrict__ basis) {
    int i = blockIdx.x * 256 + threadIdx.x;            // 256*320
    if (i >= 256 * 320) return;
    int k = i / 320, j = i - k * 320;
    float v = 0.f;
    if (j < 258) {
        int f = j >> 1, im = j & 1;
        v = rna(basis[(im ? 129 + f : f) * 256 + k]);
    }
    g_Bstft[i] = v;
}
__global__ void k_prepB1(const float* __restrict__ w) {
    int i = blockIdx.x * 256 + threadIdx.x;            // 400*128
    if (i >= 400 * 128) return;
    int kk = i >> 7, o = i & 127;
    g_B1[i] = (kk < 387) ? rna(w[o * 387 + kk]) : 0.f;
}
__global__ void k_prepB2(const float* __restrict__ w) {
    int i = blockIdx.x * 256 + threadIdx.x;            // 384*64
    if (i >= 384 * 64) return;
    int kk = i >> 6, o = i & 63;
    g_B2[i] = rna(w[o * 384 + kk]);
}
__global__ void k_prepB3(const float* __restrict__ w) {
    int i = blockIdx.x * 256 + threadIdx.x;            // 192*64
    if (i >= 192 * 64) return;
    int kk = i >> 6, o = i & 63;
    g_B3[i] = rna(w[o * 192 + kk]);
}
__global__ void k_prepB4(const float* __restrict__ w) {
    int i = blockIdx.x * 256 + threadIdx.x;            // 192*128
    if (i >= 192 * 128) return;
    int kk = i >> 7, o = i & 127;
    g_B4[i] = rna(w[o * 192 + kk]);
}
__global__ void k_prepBg(const float* __restrict__ wi, const float* __restrict__ wf,
                         const float* __restrict__ wg, const float* __restrict__ wo,
                         const float* __restrict__ ui, const float* __restrict__ uf,
                         const float* __restrict__ ug, const float* __restrict__ uo) {
    int i = blockIdx.x * 256 + threadIdx.x;            // 256*512
    if (i >= 256 * 512) return;
    int k = i >> 9, n = i & 511;
    int mat = n >> 7, o = n & 127;
    const float* W = (mat == 0) ? wi : (mat == 1) ? wf : (mat == 2) ? wg : wo;
    const float* U = (mat == 0) ? ui : (mat == 1) ? uf : (mat == 2) ? ug : uo;
    g_Bg[i] = rna((k < 128) ? W[o * 128 + k] : U[o * 128 + (k - 128)]);
}
// im2col from activations. one block per output row.
__global__ void k_prepA1() {
    int row = blockIdx.x;                              // 32768 rows, 400 cols
    int b = row >> 2, t = row & 3;
    for (int col = threadIdx.x; col < 400; col += 128) {
        float v = 0.f;
        if (col < 387) {
            int c = col / 3, k = col - 3 * c;
            int ts = t + k - 1;
            if (ts >= 0 && ts < 4) v = rna(g_mag[(b * 4 + ts) * 129 + c]);
        }
        g_A1[row * 400 + col] = v;
    }
}
__global__ void k_prepA2() {
    int row = blockIdx.x;                              // 16384 rows, 384 cols
    int b = row >> 1, t2 = row & 1;
    for (int col = threadIdx.x; col < 384; col += 128) {
        int c = col / 3, k = col - 3 * c;
        int ts = 2 * t2 + k - 1;
        float v = 0.f;
        if (ts >= 0 && ts < 4) v = rna(g_e1[(b * 4 + ts) * 128 + c]);
        g_A2[row * 384 + col] = v;
    }
}
__global__ void k_prepA3() {
    int b = blockIdx.x;                                // 8192 rows, 192 cols
    for (int col = threadIdx.x; col < 192; col += 128) {
        int c = col / 3, k = col - 3 * c;
        float v = 0.f;
        if (k >= 1) v = rna(g_e2[(b * 2 + (k - 1)) * 64 + c]);
        g_A3[b * 192 + col] = v;
    }
}
__global__ void k_prepA4() {
    int b = blockIdx.x;                                // 8192 rows, 192 cols
    for (int col = threadIdx.x; col < 192; col += 128) {
        int c = col / 3, k = col - 3 * c;
        float v = (k == 1) ? rna(g_e3[b * 64 + c]) : 0.f;
        g_A4[b * 192 + col] = v;
    }
}
__global__ void k_prepAgh(const float* __restrict__ h) {
    int b = blockIdx.x;
    g_Ag[b * 256 + 128 + threadIdx.x] = rna(h[b * 128 + threadIdx.x]);
}

// ================= generic tf32 tensor-core GEMM =================
// C[M][ldc] (+bias/relu/rna or mag epilogue) = A[M][K] * B[K][Npad]
// CTA tile 128x64, BK=16, 8 warps (4M x 2N), warp tile 32x32, mma m16n8k8.
#define MODE_PLAIN 0
#define MODE_BRELU 1
#define MODE_BRELU_RNA 2
#define MODE_MAG 3

__device__ __forceinline__ void mma_tf32(float (&d)[4], const uint32_t (&a)[4], const uint32_t (&b)[2]) {
    asm volatile("mma.sync.aligned.m16n8k8.row.col.f32.tf32.tf32.f32 "
                 "{%0,%1,%2,%3}, {%4,%5,%6,%7}, {%8,%9}, {%0,%1,%2,%3};"
                 : "+f"(d[0]), "+f"(d[1]), "+f"(d[2]), "+f"(d[3])
                 : "r"(a[0]), "r"(a[1]), "r"(a[2]), "r"(a[3]), "r"(b[0]), "r"(b[1]));
}

__global__ __launch_bounds__(256) void k_gemm(const float* __restrict__ A,
                                              const float* __restrict__ B,
                                              float* __restrict__ C,
                                              const float* __restrict__ bias,
                                              int K, int Npad, int ldc, int mode) {
    __shared__ float As[2][16][132];
    __shared__ float Bs[2][16][68];
    const int m0 = blockIdx.x * 128;
    const int n0 = blockIdx.y * 64;
    const int tid = threadIdx.x, lane = tid & 31, warp = tid >> 5;
    const int wm = warp >> 1, wn = warp & 1;
    const int r = lane >> 2, q = lane & 3;
    // loader mapping
    const int am = tid >> 1, akq = (tid & 1) * 8;      // A: row am, 8 k's
    const int bk = tid >> 4, bn = (tid & 15) * 4;      // B: row bk, 4 n's

    const float* Abase = A + (long)(m0 + am) * K + akq;
    const float* Bbase = B + (long)bk * Npad + n0 + bn;

    float4 pa0 = *(const float4*)(Abase);
    float4 pa1 = *(const float4*)(Abase + 4);
    float4 pb  = *(const float4*)(Bbase);

    float acc[2][4][4] = {};
    int buf = 0;
    // store tile 0
    {
        float av[8] = {pa0.x, pa0.y, pa0.z, pa0.w, pa1.x, pa1.y, pa1.z, pa1.w};
#pragma unroll
        for (int j = 0; j < 8; j++) As[0][akq + j][am] = av[j];
        *(float4*)&Bs[0][bk][bn] = pb;
    }
    __syncthreads();

    for (int k0 = 0; k0 < K; k0 += 16) {
        const bool has = (k0 + 16) < K;
        if (has) {
            pa0 = *(const float4*)(Abase + k0 + 16);
            pa1 = *(const float4*)(Abase + k0 + 20);
            pb  = *(const float4*)(Bbase + (long)(k0 + 16) * Npad);
        }
        // compute on smem[buf]
#pragma unroll
        for (int kq = 0; kq < 16; kq += 8) {
            uint32_t af[2][4];
            uint32_t bf[4][2];
#pragma unroll
            for (int mi = 0; mi < 2; mi++) {
                int mb = wm * 32 + mi * 16 + r;
                af[mi][0] = __float_as_uint(As[buf][kq + q][mb]);
                af[mi][1] = __float_as_uint(As[buf][kq + q][mb + 8]);
                af[mi][2] = __float_as_uint(As[buf][kq + q + 4][mb]);
                af[mi][3] = __float_as_uint(As[buf][kq + q + 4][mb + 8]);
            }
#pragma unroll
            for (int ni = 0; ni < 4; ni++) {
                int nb = wn * 32 + ni * 8 + r;
                bf[ni][0] = __float_as_uint(Bs[buf][kq + q][nb]);
                bf[ni][1] = __float_as_uint(Bs[buf][kq + q + 4][nb]);
            }
#pragma unroll
            for (int mi = 0; mi < 2; mi++)
#pragma unroll
                for (int ni = 0; ni < 4; ni++)
                    mma_tf32(acc[mi][ni], af[mi], bf[ni]);
        }
        if (has) {
            float av[8] = {pa0.x, pa0.y, pa0.z, pa0.w, pa1.x, pa1.y, pa1.z, pa1.w};
#pragma unroll
            for (int j = 0; j < 8; j++) As[buf ^ 1][akq + j][am] = av[j];
            *(float4*)&Bs[buf ^ 1][bk][bn] = pb;
        }
        __syncthreads();
        buf ^= 1;
    }

    // epilogue
#pragma unroll
    for (int mi = 0; mi < 2; mi++) {
        int row = m0 + wm * 32 + mi * 16 + r;
#pragma unroll
        for (int ni = 0; ni < 4; ni++) {
            int col = n0 + wn * 32 + ni * 8 + q * 2;
            float c0 = acc[mi][ni][0], c1 = acc[mi][ni][1];
            float c2 = acc[mi][ni][2], c3 = acc[mi][ni][3];
            if (mode == MODE_MAG) {
                int f = col >> 1;
                if (f < 129) {
                    C[(long)row * 129 + f]       = sqrtf(c0 * c0 + c1 * c1);
                    C[(long)(row + 8) * 129 + f] = sqrtf(c2 * c2 + c3 * c3);
                }
            } else {
                float b0 = 0.f, b1 = 0.f;
                if (bias) { b0 = __ldg(bias + col); b1 = __ldg(bias + col + 1); }
                float v0 = c0 + b0, v1 = c1 + b1, v2 = c2 + b0, v3 = c3 + b1;
                if (mode >= MODE_BRELU) {
                    v0 = fmaxf(v0, 0.f); v1 = fmaxf(v1, 0.f);
                    v2 = fmaxf(v2, 0.f); v3 = fmaxf(v3, 0.f);
                }
                if (mode == MODE_BRELU_RNA) {
                    v0 = rna(v0); v1 = rna(v1); v2 = rna(v2); v3 = rna(v3);
                }
                *(float2*)&C[(long)row * ldc + col]       = make_float2(v0, v1);
                *(float2*)&C[(long)(row + 8) * ldc + col] = make_float2(v2, v3);
            }
        }
    }
}

// ================= final: LSTM cell + head =================
__global__ __launch_bounds__(128) void k_final(const float* __restrict__ cin,
    const float* __restrict__ bxi, const float* __restrict__ bxf,
    const float* __restrict__ bxg, const float* __restrict__ bxo,
    const float* __restrict__ bhi, const float* __restrict__ bhf,
    const float* __restrict__ bhg, const float* __restrict__ bho,
    const float* __restrict__ cw, const float* __restrict__ cb,
    float* __restrict__ out, int writeHC) {
    const int b = blockIdx.x, o = threadIdx.x;
    const float* g = g_gt + b * 512;
    float pi = g[o]       + __ldg(bxi + o) + __ldg(bhi + o);
    float pf = g[128 + o] + __ldg(bxf + o) + __ldg(bhf + o);
    float pg = g[256 + o] + __ldg(bxg + o) + __ldg(bhg + o);
    float po = g[384 + o] + __ldg(bxo + o) + __ldg(bho + o);
    float ig = 1.f / (1.f + expf(-pi));
    float fg = 1.f / (1.f + expf(-pf));
    float gg = tanhf(pg);
    float og = 1.f / (1.f + expf(-po));
    float co = fg * cin[b * 128 + o] + ig * gg;
    float ho = og * tanhf(co);
    if (writeHC) {
        out[BATCH + b * 128 + o] = ho;
        out[BATCH + BATCH * 128 + b * 128 + o] = co;
    }
    __shared__ float red[128];
    float y = ho > 0.f ? ho : 0.f;
    red[o] = y * __ldg(cw + o);
    __syncthreads();
    for (int s = 64; s > 0; s >>= 1) {
        if (o < s) red[o] += red[o + s];
        __syncthreads();
    }
    if (o == 0) out[b] = 1.f / (1.f + expf(-(red[0] + cb[0])));
}

// ================= launch =================
extern "C" void kernel_launch(void* const* d_in, const int* in_sizes, int n_in,
                              void* d_out, int out_size) {
    const float* audio = (const float*)d_in[0];
    const float* h     = (const float*)d_in[1];
    const float* cin   = (const float*)d_in[2];
    const float* basis = (const float*)d_in[3];
    const float* w1 = (const float*)d_in[4];  const float* b1 = (const float*)d_in[5];
    const float* w2 = (const float*)d_in[6];  const float* b2 = (const float*)d_in[7];
    const float* w3 = (const float*)d_in[8];  const float* b3 = (const float*)d_in[9];
    const float* w4 = (const float*)d_in[10]; const float* b4 = (const float*)d_in[11];
    const float* wi = (const float*)d_in[12]; const float* wf = (const float*)d_in[13];
    const float* wg = (const float*)d_in[14]; const float* wo = (const float*)d_in[15];
    const float* ui = (const float*)d_in[16]; const float* uf = (const float*)d_in[17];
    const float* ug = (const float*)d_in[18]; const float* uo = (const float*)d_in[19];
    const float* bxi = (const float*)d_in[20]; const float* bxf = (const float*)d_in[21];
    const float* bxg = (const float*)d_in[22]; const float* bxo = (const float*)d_in[23];
    const float* bhi = (const float*)d_in[24]; const float* bhf = (const float*)d_in[25];
    const float* bhg = (const float*)d_in[26]; const float* bho = (const float*)d_in[27];
    const float* cw  = (const float*)d_in[28]; const float* cb  = (const float*)d_in[29];
    float* out = (float*)d_out;
    int writeHC = (out_size >= BATCH * 257) ? 1 : 0;

    float *pAstft, *pBstft, *pA1, *pB1, *pA2, *pB2, *pA3, *pB3, *pA4, *pB4, *pAg, *pBg;
    float *pMag, *pE1, *pE2, *pE3, *pGt;
    cudaGetSymbolAddress((void**)&pAstft, g_Astft);
    cudaGetSymbolAddress((void**)&pBstft, g_Bstft);
    cudaGetSymbolAddress((void**)&pA1, g_A1);  cudaGetSymbolAddress((void**)&pB1, g_B1);
    cudaGetSymbolAddress((void**)&pA2, g_A2);  cudaGetSymbolAddress((void**)&pB2, g_B2);
    cudaGetSymbolAddress((void**)&pA3, g_A3);  cudaGetSymbolAddress((void**)&pB3, g_B3);
    cudaGetSymbolAddress((void**)&pA4, g_A4);  cudaGetSymbolAddress((void**)&pB4, g_B4);
    cudaGetSymbolAddress((void**)&pAg, g_Ag);  cudaGetSymbolAddress((void**)&pBg, g_Bg);
    cudaGetSymbolAddress((void**)&pMag, g_mag);
    cudaGetSymbolAddress((void**)&pE1, g_e1);
    cudaGetSymbolAddress((void**)&pE2, g_e2);
    cudaGetSymbolAddress((void**)&pE3, g_e3);
    cudaGetSymbolAddress((void**)&pGt, g_gt);

    // weight packing (independent of activation chain)
    k_prepBstft<<<(256 * 320 + 255) / 256, 256>>>(basis);
    k_prepB1<<<(400 * 128 + 255) / 256, 256>>>(w1);
    k_prepB2<<<(384 * 64 + 255) / 256, 256>>>(w2);
    k_prepB3<<<(192 * 64 + 255) / 256, 256>>>(w3);
    k_prepB4<<<(192 * 128 + 255) / 256, 256>>>(w4);
    k_prepBg<<<(256 * 512 + 255) / 256, 256>>>(wi, wf, wg, wo, ui, uf, ug, uo);
    k_prepAgh<<<8192, 128>>>(h);

    // STFT + mag
    k_prepAstft<<<32768, 256>>>(audio);
    { dim3 gr(256, 5); k_gemm<<<gr, 256>>>(pAstft, pBstft, pMag, nullptr, 256, 320, 129, MODE_MAG); }
    // enc1
    k_prepA1<<<32768, 128>>>();
    { dim3 gr(256, 2); k_gemm<<<gr, 256>>>(pA1, pB1, pE1, b1, 400, 128, 128, MODE_BRELU); }
    // enc2
    k_prepA2<<<16384, 128>>>();
    { dim3 gr(128, 1); k_gemm<<<gr, 256>>>(pA2, pB2, pE2, b2, 384, 64, 64, MODE_BRELU); }
    // enc3
    k_prepA3<<<8192, 128>>>();
    { dim3 gr(64, 1); k_gemm<<<gr, 256>>>(pA3, pB3, pE3, b3, 192, 64, 64, MODE_BRELU); }
    // enc4 -> x, written rna'd into g_Ag[:, 0:128]
    k_prepA4<<<8192, 128>>>();
    { dim3 gr(64, 2); k_gemm<<<gr, 256>>>(pA4, pB4, pAg, b4, 192, 128, 256, MODE_BRELU_RNA); }
    // gates
    { dim3 gr(64, 8); k_gemm<<<gr, 256>>>(pAg, pBg, pGt, nullptr, 256, 512, 512, MODE_PLAIN); }
    // LSTM cell + head
    k_final<<<BATCH, 128>>>(cin, bxi, bxf, bxg, bxo, bhi, bhf, bhg, bho, cw, cb, out, writeHC);
}